// round 7
// baseline (speedup 1.0000x reference)
#include <cuda_runtime.h>
#include <math.h>

#define BB   128
#define NN   1024
#define DIN  192
#define HH   128
#define KK   3
#define BN   (BB*NN)
#define NSUB 8
#define SCALE 0.08838834764831845f   // 1/sqrt(128)
#define LNEPS 1e-5f

// ------------------------- device scratch ------------------------------------
__device__ float g_inputs[(size_t)BN * HH];     // 64 MB
__device__ float g_WpT[DIN * HH];
__device__ float g_WqT[HH * HH];
__device__ float g_WvT[HH * HH];
__device__ float g_WihT[HH * 3 * HH];
__device__ float g_WhhT[HH * 3 * HH];
__device__ float g_W1T[HH * 2 * HH];
__device__ float g_W2T[2 * HH * HH];
__device__ float g_slots[BB * KK * HH];
__device__ float g_qk[BB * KK * HH];
__device__ float g_qc[BB * KK];
__device__ float g_updp[BB * NSUB * KK * HH];   // per-sub partial updates (1.5 MB)
__device__ float g_sumwp[BB * NSUB * KK];

typedef unsigned long long u64;

__device__ __forceinline__ u64 pack2(float lo, float hi) {
    u64 r; asm("mov.b64 %0, {%1,%2};" : "=l"(r) : "f"(lo), "f"(hi)); return r;
}
__device__ __forceinline__ void unpack2(u64 v, float& lo, float& hi) {
    asm("mov.b64 {%0,%1}, %2;" : "=f"(lo), "=f"(hi) : "l"(v));
}
__device__ __forceinline__ u64 fma2(u64 a, u64 b, u64 c) {
    u64 d; asm("fma.rn.f32x2 %0, %1, %2, %3;" : "=l"(d) : "l"(a), "l"(b), "l"(c)); return d;
}
__device__ __forceinline__ float wred(float v) {
    #pragma unroll
    for (int o = 16; o; o >>= 1) v += __shfl_xor_sync(0xFFFFFFFFu, v, o);
    return v;
}
__device__ __forceinline__ float sigmoidf_(float x) { return 1.0f / (1.0f + expf(-x)); }
__device__ __forceinline__ float gelu_exact(float x) {
    return 0.5f * x * (1.0f + erff(x * 0.7071067811865476f));
}

// ------------------------- weight transposes ---------------------------------
__global__ void prep_transpose(const float* __restrict__ Wp, const float* __restrict__ Wq,
                               const float* __restrict__ Wv, const float* __restrict__ Wih,
                               const float* __restrict__ Whh, const float* __restrict__ W1,
                               const float* __restrict__ W2) {
    int i = blockIdx.x * blockDim.x + threadIdx.x;
    int stride = gridDim.x * blockDim.x;
    for (int t = i; t < HH * DIN; t += stride) { int j = t / DIN, e = t % DIN; g_WpT[e * HH + j] = Wp[t]; }
    for (int t = i; t < HH * HH; t += stride) { int j = t / HH, e = t % HH; g_WqT[e * HH + j] = Wq[t]; }
    for (int t = i; t < HH * HH; t += stride) { int d = t / HH, e = t % HH; g_WvT[e * HH + d] = Wv[t]; }
    for (int t = i; t < 3 * HH * HH; t += stride) { int o = t / HH, d = t % HH; g_WihT[d * (3 * HH) + o] = Wih[t]; }
    for (int t = i; t < 3 * HH * HH; t += stride) { int o = t / HH, d = t % HH; g_WhhT[d * (3 * HH) + o] = Whh[t]; }
    for (int t = i; t < 2 * HH * HH; t += stride) { int p = t / HH, d = t % HH; g_W1T[d * (2 * HH) + p] = W1[t]; }
    for (int t = i; t < 2 * HH * HH; t += stride) { int j = t / (2 * HH), p = t % (2 * HH); g_W2T[p * HH + j] = W2[t]; }
}

// ------------------------- init slots + LN + q + qk + c (iteration 0) --------
// grid = BB, 512 threads. Writes g_slots, g_qk (scaled), g_qc.
__global__ __launch_bounds__(512) void init_lnq_kernel(const float* __restrict__ noise,
                                                       const float* __restrict__ smu,
                                                       const float* __restrict__ sls,
                                                       const float* __restrict__ gs,
                                                       const float* __restrict__ bs,
                                                       const float* __restrict__ bq,
                                                       const float* __restrict__ Wk,
                                                       const float* __restrict__ bk) {
    const int b = blockIdx.x;
    const int tid = threadIdx.x;
    const int wid = tid >> 5, lane = tid & 31;
    __shared__ float s_s[KK][HH];
    __shared__ float q_s[KK][HH];
    __shared__ float sl_s[KK * HH];
    __shared__ float part_s[4][KK][HH];
    __shared__ float red1[12], red2[12];

    if (tid < KK * HH) {
        float v = smu[tid] + expf(sls[tid]) * noise[b * KK * HH + tid];
        sl_s[tid] = v;
        g_slots[b * KK * HH + tid] = v;
        float a = wred(v), a2 = wred(v * v);
        if (lane == 0) { red1[wid] = a; red2[wid] = a2; }
    }
    __syncthreads();
    if (tid < KK * HH) {
        const int ka = tid >> 7, j = tid & 127;
        float mu = (red1[ka*4] + red1[ka*4+1] + red1[ka*4+2] + red1[ka*4+3]) * (1.0f / HH);
        float var = (red2[ka*4] + red2[ka*4+1] + red2[ka*4+2] + red2[ka*4+3]) * (1.0f / HH) - mu * mu;
        float rstd = rsqrtf(var + LNEPS);
        s_s[ka][j] = (sl_s[tid] - mu) * rstd * gs[j] + bs[j];
    }
    __syncthreads();
    // q = s@Wq^T + bq, split-K4
    {
        const int j = tid & 127, part = tid >> 7;
        const int e0 = part * 32;
        float a0 = 0.f, a1 = 0.f, a2 = 0.f;
        #pragma unroll 8
        for (int e = 0; e < 32; e++) {
            float wv = g_WqT[(e0 + e) * HH + j];
            a0 += s_s[0][e0 + e] * wv;
            a1 += s_s[1][e0 + e] * wv;
            a2 += s_s[2][e0 + e] * wv;
        }
        part_s[part][0][j] = a0; part_s[part][1][j] = a1; part_s[part][2][j] = a2;
    }
    __syncthreads();
    if (tid < KK * HH) {
        const int ka = tid >> 7, j = tid & 127;
        float s = bq[j];
        #pragma unroll
        for (int p = 0; p < 4; p++) s += part_s[p][ka][j];
        q_s[ka][j] = s;
    }
    __syncthreads();
    // qk = SCALE * q@Wk, split-K4
    {
        const int j = tid & 127, part = tid >> 7;
        const int d0 = part * 32;
        float a0 = 0.f, a1 = 0.f, a2 = 0.f;
        #pragma unroll 8
        for (int d = 0; d < 32; d++) {
            float wv = Wk[(d0 + d) * HH + j];
            a0 += q_s[0][d0 + d] * wv;
            a1 += q_s[1][d0 + d] * wv;
            a2 += q_s[2][d0 + d] * wv;
        }
        part_s[part][0][j] = a0; part_s[part][1][j] = a1; part_s[part][2][j] = a2;
    }
    __syncthreads();
    if (tid < KK * HH) {
        const int ka = tid >> 7, j = tid & 127;
        float s = 0.f;
        #pragma unroll
        for (int p = 0; p < 4; p++) s += part_s[p][ka][j];
        g_qk[b * KK * HH + tid] = s * SCALE;
        float pr = wred(q_s[ka][j] * bk[j]);
        if (lane == 0) red1[wid] = pr;
    }
    __syncthreads();
    if (tid < KK)
        g_qc[b * KK + tid] = (red1[tid*4] + red1[tid*4+1] + red1[tid*4+2] + red1[tid*4+3]) * SCALE;
}

// ------------------------- fused projection + LayerNorm (f32x2) --------------
#define TM 64
#define KB 16
__global__ __launch_bounds__(256) void proj_ln_kernel(const float* __restrict__ X,
                                                      const float* __restrict__ bp,
                                                      const float* __restrict__ gin,
                                                      const float* __restrict__ bin) {
    __shared__ __align__(16) float xs_t[KB][66];
    __shared__ __align__(16) float ws[KB][HH];
    const int row0 = blockIdx.x * TM;
    const int tid = threadIdx.x;
    const int w = tid >> 5;
    const int l = tid & 31;

    u64 acc[4][4];
    #pragma unroll
    for (int p = 0; p < 4; p++)
        #pragma unroll
        for (int c = 0; c < 4; c++) acc[p][c] = pack2(0.0f, 0.0f);

    const int ld_row = tid >> 2;
    const int ld_seg = tid & 3;

    for (int k0 = 0; k0 < DIN; k0 += KB) {
        float4 xv = *(const float4*)(&X[(size_t)(row0 + ld_row) * DIN + k0 + ld_seg * 4]);
        xs_t[ld_seg * 4 + 0][ld_row] = xv.x;
        xs_t[ld_seg * 4 + 1][ld_row] = xv.y;
        xs_t[ld_seg * 4 + 2][ld_row] = xv.z;
        xs_t[ld_seg * 4 + 3][ld_row] = xv.w;
        #pragma unroll
        for (int i = 0; i < 2; i++) {
            int lin = i * 256 + tid;
            int kk = lin >> 5, jj = lin & 31;
            *(float4*)(&ws[kk][jj * 4]) = *(const float4*)(&g_WpT[(k0 + kk) * HH + jj * 4]);
        }
        __syncthreads();
        #pragma unroll
        for (int kk = 0; kk < KB; kk++) {
            float4 b4 = *(const float4*)(&ws[kk][l * 4]);
            u64 bx = pack2(b4.x, b4.x);
            u64 by = pack2(b4.y, b4.y);
            u64 bz = pack2(b4.z, b4.z);
            u64 bw = pack2(b4.w, b4.w);
            #pragma unroll
            for (int p = 0; p < 4; p++) {
                u64 a = *(const u64*)(&xs_t[kk][w * 8 + p * 2]);
                acc[p][0] = fma2(a, bx, acc[p][0]);
                acc[p][1] = fma2(a, by, acc[p][1]);
                acc[p][2] = fma2(a, bz, acc[p][2]);
                acc[p][3] = fma2(a, bw, acc[p][3]);
            }
        }
        __syncthreads();
    }

    const float4 bias = *(const float4*)(&bp[l * 4]);
    const float4 g4   = *(const float4*)(&gin[l * 4]);
    const float4 b4n  = *(const float4*)(&bin[l * 4]);

    #pragma unroll
    for (int p = 0; p < 4; p++) {
        float r0[4], r1[4];
        unpack2(acc[p][0], r0[0], r1[0]);
        unpack2(acc[p][1], r0[1], r1[1]);
        unpack2(acc[p][2], r0[2], r1[2]);
        unpack2(acc[p][3], r0[3], r1[3]);
        #pragma unroll
        for (int half = 0; half < 2; half++) {
            float* r = half ? r1 : r0;
            r[0] += bias.x; r[1] += bias.y; r[2] += bias.z; r[3] += bias.w;
            float s  = r[0] + r[1] + r[2] + r[3];
            float s2 = r[0]*r[0] + r[1]*r[1] + r[2]*r[2] + r[3]*r[3];
            s = wred(s); s2 = wred(s2);
            float mu = s * (1.0f / HH);
            float var = s2 * (1.0f / HH) - mu * mu;
            float rstd = rsqrtf(var + LNEPS);
            int row = row0 + w * 8 + p * 2 + half;
            float4 o;
            o.x = (r[0] - mu) * rstd * g4.x + b4n.x;
            o.y = (r[1] - mu) * rstd * g4.y + b4n.y;
            o.z = (r[2] - mu) * rstd * g4.z + b4n.z;
            o.w = (r[3] - mu) * rstd * g4.w + b4n.w;
            *(float4*)(&g_inputs[(size_t)row * HH + l * 4]) = o;
        }
    }
}

// ------------------------- attention stream (8 sub-CTAs per batch) -----------
// grid = BB*NSUB, 512 threads. Reads g_qk/g_qc, streams 128 tokens, writes
// attn rows + per-sub partial updates to g_updp / g_sumwp.
__global__ __launch_bounds__(512) void attn_stream_kernel(float* __restrict__ attn_out) {
    const int bx = blockIdx.x;
    const int b = bx >> 3, sub = bx & (NSUB - 1);
    const int tid = threadIdx.x;
    const int wid = tid >> 5, lane = tid & 31;
    __shared__ float qk_s[KK * HH];
    __shared__ float c_s[KK];
    __shared__ float a_s[KK][128];
    __shared__ float wacc[16][KK][HH];
    __shared__ float wsum_s[16][KK];

    if (tid < KK * HH) qk_s[tid] = g_qk[b * KK * HH + tid];
    if (tid < KK) c_s[tid] = g_qc[b * KK + tid];
    __syncthreads();

    const int hw = tid >> 4;        // half-warp 0..31
    const int lh = tid & 15;
    float qv[KK][8];
    #pragma unroll
    for (int ka = 0; ka < KK; ka++)
        #pragma unroll
        for (int q = 0; q < 8; q++) qv[ka][q] = qk_s[ka * HH + lh * 8 + q];
    const float c0 = c_s[0], c1 = c_s[1], c2 = c_s[2];

    float f[KK][8];
    #pragma unroll
    for (int ka = 0; ka < KK; ka++)
        #pragma unroll
        for (int q = 0; q < 8; q++) f[ka][q] = 0.f;
    float ws0 = 0.f, ws1 = 0.f, ws2 = 0.f;

    const float* inp = g_inputs + (size_t)b * NN * HH;
    const int n0 = sub * 128;
    #pragma unroll 2
    for (int t = 0; t < 4; t++) {
        int nl = t * 32 + hw;                 // local token 0..127
        int n = n0 + nl;
        float4 x0 = *(const float4*)(&inp[(size_t)n * HH + lh * 8]);
        float4 x1 = *(const float4*)(&inp[(size_t)n * HH + lh * 8 + 4]);
        float xr[8] = {x0.x, x0.y, x0.z, x0.w, x1.x, x1.y, x1.z, x1.w};
        float d0 = 0.f, d1 = 0.f, d2 = 0.f;
        #pragma unroll
        for (int q = 0; q < 8; q++) {
            d0 += xr[q] * qv[0][q];
            d1 += xr[q] * qv[1][q];
            d2 += xr[q] * qv[2][q];
        }
        #pragma unroll
        for (int o = 1; o < 16; o <<= 1) {
            d0 += __shfl_xor_sync(0xFFFFFFFFu, d0, o);
            d1 += __shfl_xor_sync(0xFFFFFFFFu, d1, o);
            d2 += __shfl_xor_sync(0xFFFFFFFFu, d2, o);
        }
        d0 += c0; d1 += c1; d2 += c2;
        float m = fmaxf(d0, fmaxf(d1, d2));
        float e0 = expf(d0 - m), e1 = expf(d1 - m), e2 = expf(d2 - m);
        float inv = 1.0f / (e0 + e1 + e2);
        float a0 = e0 * inv, a1 = e1 * inv, a2 = e2 * inv;
        if (lh == 0) { a_s[0][nl] = a0; a_s[1][nl] = a1; a_s[2][nl] = a2; }
        #pragma unroll
        for (int q = 0; q < 8; q++) {
            f[0][q] += a0 * xr[q];
            f[1][q] += a1 * xr[q];
            f[2][q] += a2 * xr[q];
        }
        ws0 += a0; ws1 += a1; ws2 += a2;
    }
    #pragma unroll
    for (int ka = 0; ka < KK; ka++)
        #pragma unroll
        for (int q = 0; q < 8; q++)
            f[ka][q] += __shfl_xor_sync(0xFFFFFFFFu, f[ka][q], 16);
    ws0 += __shfl_xor_sync(0xFFFFFFFFu, ws0, 16);
    ws1 += __shfl_xor_sync(0xFFFFFFFFu, ws1, 16);
    ws2 += __shfl_xor_sync(0xFFFFFFFFu, ws2, 16);
    if (lane < 16) {
        #pragma unroll
        for (int ka = 0; ka < KK; ka++)
            #pragma unroll
            for (int q = 0; q < 8; q++)
                wacc[wid][ka][lane * 8 + q] = f[ka][q];
    }
    if (lane == 0) { wsum_s[wid][0] = ws0; wsum_s[wid][1] = ws1; wsum_s[wid][2] = ws2; }
    __syncthreads();

    if (tid < KK * HH) {
        const int ka = tid >> 7, e = tid & 127;
        float s = 0.f;
        #pragma unroll
        for (int ww = 0; ww < 16; ww++) s += wacc[ww][ka][e];
        g_updp[bx * KK * HH + tid] = s;
    }
    if (tid < KK) {
        float s = 0.f;
        #pragma unroll
        for (int ww = 0; ww < 16; ww++) s += wsum_s[ww][tid];
        g_sumwp[bx * KK + tid] = s;
    }
    // attn rows: out[b][ka][n0 + i]
    if (tid < KK * 128) {
        const int ka = tid >> 7, i = tid & 127;
        attn_out[(size_t)b * KK * NN + ka * NN + n0 + i] = a_s[ka][i];
    }
}

// ------------------------- updates -> GRU -> LN -> MLP -> next qk ------------
// grid = BB, 1024 threads.
__global__ __launch_bounds__(1024) void post_kernel(const float* __restrict__ bv,
                                                    const float* __restrict__ bih,
                                                    const float* __restrict__ bhh,
                                                    const float* __restrict__ gm,
                                                    const float* __restrict__ bm,
                                                    const float* __restrict__ b1,
                                                    const float* __restrict__ b2,
                                                    const float* __restrict__ gs,
                                                    const float* __restrict__ bs,
                                                    const float* __restrict__ bq,
                                                    const float* __restrict__ Wk,
                                                    const float* __restrict__ bk,
                                                    float* __restrict__ out_slots) {
    const int b = blockIdx.x;
    const int tid = threadIdx.x;
    const int wid = tid >> 5, lane = tid & 31;
    __shared__ float upd_s[KK][HH];          // also reused as s_s in tail
    __shared__ float h_s[KK][HH];
    __shared__ float x_s[KK][HH];            // also reused as q_s in tail
    __shared__ float gi_s[KK][3 * HH];
    __shared__ float gh_s[KK][3 * HH];
    __shared__ float hn_s[KK][HH];
    __shared__ float m_s[KK][HH];            // reused for new-slot stash in tail
    __shared__ float t_s[KK][2 * HH];
    __shared__ float part_s[8][KK][2 * HH];  // 24 KB split-K scratch
    __shared__ float sw_s[KK];
    __shared__ float red1[12], red2[12];

    // ---- Phase 0: reduce per-sub partials
    if (tid < KK * HH) {
        float s = 0.f;
        #pragma unroll
        for (int sub = 0; sub < NSUB; sub++)
            s += g_updp[(b * NSUB + sub) * KK * HH + tid];
        upd_s[0][tid] = s;                   // flat
        h_s[0][tid] = g_slots[b * KK * HH + tid];
    }
    if (tid < KK) {
        float s = 0.f;
        #pragma unroll
        for (int sub = 0; sub < NSUB; sub++) s += g_sumwp[(b * NSUB + sub) * KK + tid];
        sw_s[tid] = s;
    }
    __syncthreads();

    // ---- Phase 1: x = upd @ Wv^T + sumw*bv (split-K8)
    {
        const int j = tid & 127, part = tid >> 7;
        float a0 = 0.f, a1 = 0.f, a2 = 0.f;
        const int e0 = part * 16;
        #pragma unroll
        for (int e = 0; e < 16; e++) {
            float wv = g_WvT[(e0 + e) * HH + j];
            a0 += upd_s[0][e0 + e] * wv;
            a1 += upd_s[1][e0 + e] * wv;
            a2 += upd_s[2][e0 + e] * wv;
        }
        part_s[part][0][j] = a0; part_s[part][1][j] = a1; part_s[part][2][j] = a2;
    }
    __syncthreads();
    if (tid < KK * HH) {
        const int ka = tid >> 7, j = tid & 127;
        float s = sw_s[ka] * bv[j];
        #pragma unroll
        for (int p = 0; p < 8; p++) s += part_s[p][ka][j];
        x_s[ka][j] = s;
    }
    __syncthreads();

    // ---- Phase 2: GRU gates
    if (tid < 768) {
        const int is_hh = tid >= 384;
        const int o = is_hh ? tid - 384 : tid;
        const float* W = is_hh ? g_WhhT : g_WihT;
        const float (*src)[HH] = is_hh ? h_s : x_s;
        float a0 = 0.f, a1 = 0.f, a2 = 0.f;
        #pragma unroll 4
        for (int d = 0; d < HH; d++) {
            float wv = W[d * 384 + o];
            a0 += src[0][d] * wv;
            a1 += src[1][d] * wv;
            a2 += src[2][d] * wv;
        }
        if (is_hh) {
            float bb = bhh[o];
            gh_s[0][o] = a0 + bb; gh_s[1][o] = a1 + bb; gh_s[2][o] = a2 + bb;
        } else {
            float bb = bih[o];
            gi_s[0][o] = a0 + bb; gi_s[1][o] = a1 + bb; gi_s[2][o] = a2 + bb;
        }
    }
    __syncthreads();

    // ---- Phase 3: gate combine + LN
    if (tid < KK * HH) {
        const int ka = tid >> 7, j = tid & 127;
        float r = sigmoidf_(gi_s[ka][j]       + gh_s[ka][j]);
        float z = sigmoidf_(gi_s[ka][128 + j] + gh_s[ka][128 + j]);
        float nn = tanhf(gi_s[ka][256 + j] + r * gh_s[ka][256 + j]);
        float hnew = (1.0f - z) * nn + z * h_s[ka][j];
        hn_s[ka][j] = hnew;
        float a = wred(hnew), a2 = wred(hnew * hnew);
        if (lane == 0) { red1[wid] = a; red2[wid] = a2; }
    }
    __syncthreads();
    if (tid < KK * HH) {
        const int ka = tid >> 7, j = tid & 127;
        float mu = (red1[ka*4] + red1[ka*4+1] + red1[ka*4+2] + red1[ka*4+3]) * (1.0f / HH);
        float var = (red2[ka*4] + red2[ka*4+1] + red2[ka*4+2] + red2[ka*4+3]) * (1.0f / HH) - mu * mu;
        float rstd = rsqrtf(var + LNEPS);
        m_s[ka][j] = (hn_s[ka][j] - mu) * rstd * gm[j] + bm[j];
    }
    __syncthreads();

    // ---- Phase 4: W1 + gelu (split-K4, 256 cols)
    {
        const int p = tid & 255, part = tid >> 8;
        float a0 = 0.f, a1 = 0.f, a2 = 0.f;
        const int d0 = part * 32;
        #pragma unroll 8
        for (int d = 0; d < 32; d++) {
            float wv = g_W1T[(d0 + d) * (2 * HH) + p];
            a0 += m_s[0][d0 + d] * wv;
            a1 += m_s[1][d0 + d] * wv;
            a2 += m_s[2][d0 + d] * wv;
        }
        part_s[part][0][p] = a0; part_s[part][1][p] = a1; part_s[part][2][p] = a2;
    }
    __syncthreads();
    if (tid < KK * 2 * HH) {
        const int ka = tid >> 8, p = tid & 255;
        float s = b1[p];
        #pragma unroll
        for (int q = 0; q < 4; q++) s += part_s[q][ka][p];
        t_s[ka][p] = gelu_exact(s);
    }
    __syncthreads();

    // ---- Phase 5: W2 + residual (split-K8)
    {
        const int j = tid & 127, part = tid >> 7;
        float a0 = 0.f, a1 = 0.f, a2 = 0.f;
        const int p0 = part * 32;
        #pragma unroll 8
        for (int p = 0; p < 32; p++) {
            float wv = g_W2T[(p0 + p) * HH + j];
            a0 += t_s[0][p0 + p] * wv;
            a1 += t_s[1][p0 + p] * wv;
            a2 += t_s[2][p0 + p] * wv;
        }
        part_s[part][0][j] = a0; part_s[part][1][j] = a1; part_s[part][2][j] = a2;
    }
    __syncthreads();
    if (tid < KK * HH) {
        const int ka = tid >> 7, j = tid & 127;
        float o = hn_s[ka][j] + b2[j];
        #pragma unroll
        for (int p = 0; p < 8; p++) o += part_s[p][ka][j];
        int idx = b * KK * HH + tid;
        g_slots[idx] = o;
        out_slots[idx] = o;
        m_s[0][tid & 1023] = o;              // stash new slots (flat) for tail
    }
    __syncthreads();

    // ================= TAIL: LN/q/qk/c for the NEXT iteration =================
    if (tid < KK * HH) {
        float v = m_s[0][tid];
        float a = wred(v), a2 = wred(v * v);
        if (lane == 0) { red1[wid] = a; red2[wid] = a2; }
    }
    __syncthreads();
    if (tid < KK * HH) {
        const int ka = tid >> 7, j = tid & 127;
        float mu = (red1[ka*4] + red1[ka*4+1] + red1[ka*4+2] + red1[ka*4+3]) * (1.0f / HH);
        float var = (red2[ka*4] + red2[ka*4+1] + red2[ka*4+2] + red2[ka*4+3]) * (1.0f / HH) - mu * mu;
        float rstd = rsqrtf(var + LNEPS);
        upd_s[0][tid] = (m_s[0][tid] - mu) * rstd * gs[j] + bs[j];   // s_s (flat)
    }
    __syncthreads();
    // q = s@Wq^T + bq (split-K8)
    {
        const int j = tid & 127, part = tid >> 7;
        const int e0 = part * 16;
        float a0 = 0.f, a1 = 0.f, a2 = 0.f;
        #pragma unroll
        for (int e = 0; e < 16; e++) {
            float wv = g_WqT[(e0 + e) * HH + j];
            a0 += upd_s[0][e0 + e] * wv;
            a1 += upd_s[1][e0 + e] * wv;
            a2 += upd_s[2][e0 + e] * wv;
        }
        part_s[part][0][j] = a0; part_s[part][1][j] = a1; part_s[part][2][j] = a2;
    }
    __syncthreads();
    if (tid < KK * HH) {
        const int ka = tid >> 7, j = tid & 127;
        float s = bq[j];
        #pragma unroll
        for (int p = 0; p < 8; p++) s += part_s[p][ka][j];
        x_s[ka][j] = s;                       // q_s
    }
    __syncthreads();
    // qk = SCALE * q@Wk (split-K8)
    {
        const int j = tid & 127, part = tid >> 7;
        const int d0 = part * 16;
        float a0 = 0.f, a1 = 0.f, a2 = 0.f;
        #pragma unroll
        for (int d = 0; d < 16; d++) {
            float wv = Wk[(d0 + d) * HH + j];
            a0 += x_s[0][d0 + d] * wv;
            a1 += x_s[1][d0 + d] * wv;
            a2 += x_s[2][d0 + d] * wv;
        }
        part_s[part][0][j] = a0; part_s[part][1][j] = a1; part_s[part][2][j] = a2;
    }
    __syncthreads();
    if (tid < KK * HH) {
        const int ka = tid >> 7, j = tid & 127;
        float s = 0.f;
        #pragma unroll
        for (int p = 0; p < 8; p++) s += part_s[p][ka][j];
        g_qk[b * KK * HH + tid] = s * SCALE;
        float pr = wred(x_s[ka][j] * bk[j]);
        if (lane == 0) red1[wid] = pr;
    }
    __syncthreads();
    if (tid < KK)
        g_qc[b * KK + tid] = (red1[tid*4] + red1[tid*4+1] + red1[tid*4+2] + red1[tid*4+3]) * SCALE;
}

// ------------------------- launch --------------------------------------------
extern "C" void kernel_launch(void* const* d_in, const int* in_sizes, int n_in,
                              void* d_out, int out_size) {
    const float* X       = (const float*)d_in[0];
    const float* noise   = (const float*)d_in[1];
    const float* slot_mu = (const float*)d_in[2];
    const float* slot_ls = (const float*)d_in[3];
    const float* Wp  = (const float*)d_in[4];
    const float* bp  = (const float*)d_in[5];
    const float* gin = (const float*)d_in[6];
    const float* bin = (const float*)d_in[7];
    const float* Wq  = (const float*)d_in[8];
    const float* bq  = (const float*)d_in[9];
    const float* Wk  = (const float*)d_in[10];
    const float* bk  = (const float*)d_in[11];
    const float* Wv  = (const float*)d_in[12];
    const float* bv  = (const float*)d_in[13];
    const float* Wih = (const float*)d_in[14];
    const float* bih = (const float*)d_in[15];
    const float* Whh = (const float*)d_in[16];
    const float* bhh = (const float*)d_in[17];
    const float* gs  = (const float*)d_in[18];
    const float* bs  = (const float*)d_in[19];
    const float* W1  = (const float*)d_in[20];
    const float* b1  = (const float*)d_in[21];
    const float* W2  = (const float*)d_in[22];
    const float* b2  = (const float*)d_in[23];
    const float* gm  = (const float*)d_in[24];
    const float* bm  = (const float*)d_in[25];

    float* out_slots = (float*)d_out;
    float* out_attn  = (float*)d_out + BB * KK * HH;

    prep_transpose<<<192, 256>>>(Wp, Wq, Wv, Wih, Whh, W1, W2);
    init_lnq_kernel<<<BB, 512>>>(noise, slot_mu, slot_ls, gs, bs, bq, Wk, bk);
    proj_ln_kernel<<<BN / TM, 256>>>(X, bp, gin, bin);

    for (int it = 0; it < 3; it++) {
        attn_stream_kernel<<<BB * NSUB, 512>>>(out_attn);
        post_kernel<<<BB, 1024>>>(bv, bih, bhh, gm, bm, b1, b2,
                                  gs, bs, bq, Wk, bk, out_slots);
    }
}

// round 8
// speedup vs baseline: 1.2686x; 1.2686x over previous
#include <cuda_runtime.h>
#include <math.h>

#define BB   128
#define NN   1024
#define DIN  192
#define HH   128
#define KK   3
#define BN   (BB*NN)
#define NSUB 2
#define SCALE 0.08838834764831845f   // 1/sqrt(128)
#define LNEPS 1e-5f

// ------------------------- device scratch ------------------------------------
__device__ float g_inputs [(size_t)BN * HH];     // 64 MB, [b][n][d]
__device__ float g_inputsT[(size_t)BN * HH];     // 64 MB, [b][d][n]
__device__ float g_WpT[DIN * HH];
__device__ float g_WqT[HH * HH];
__device__ float g_WvT[HH * HH];
__device__ float g_WihT[HH * 3 * HH];
__device__ float g_WhhT[HH * 3 * HH];
__device__ float g_W1T[HH * 2 * HH];
__device__ float g_W2T[2 * HH * HH];
__device__ float g_slots[BB * KK * HH];
__device__ float g_qk[BB * KK * HH];
__device__ float g_qc[BB * KK];
__device__ float g_updp[BB * NSUB * KK * HH];
__device__ float g_sumwp[BB * NSUB * KK];

typedef unsigned long long u64;

__device__ __forceinline__ u64 pack2(float lo, float hi) {
    u64 r; asm("mov.b64 %0, {%1,%2};" : "=l"(r) : "f"(lo), "f"(hi)); return r;
}
__device__ __forceinline__ void unpack2(u64 v, float& lo, float& hi) {
    asm("mov.b64 {%0,%1}, %2;" : "=f"(lo), "=f"(hi) : "l"(v));
}
__device__ __forceinline__ u64 fma2(u64 a, u64 b, u64 c) {
    u64 d; asm("fma.rn.f32x2 %0, %1, %2, %3;" : "=l"(d) : "l"(a), "l"(b), "l"(c)); return d;
}
__device__ __forceinline__ u64 add2(u64 a, u64 b) {
    u64 d; asm("add.rn.f32x2 %0, %1, %2;" : "=l"(d) : "l"(a), "l"(b)); return d;
}
__device__ __forceinline__ u64 mul2(u64 a, u64 b) {
    u64 d; asm("mul.rn.f32x2 %0, %1, %2;" : "=l"(d) : "l"(a), "l"(b)); return d;
}
__device__ __forceinline__ float wred(float v) {
    #pragma unroll
    for (int o = 16; o; o >>= 1) v += __shfl_xor_sync(0xFFFFFFFFu, v, o);
    return v;
}
__device__ __forceinline__ u64 wred2(u64 v) {
    #pragma unroll
    for (int o = 16; o; o >>= 1) v = add2(v, __shfl_xor_sync(0xFFFFFFFFu, v, o));
    return v;
}
__device__ __forceinline__ float sigmoidf_(float x) { return 1.0f / (1.0f + expf(-x)); }
__device__ __forceinline__ float gelu_exact(float x) {
    return 0.5f * x * (1.0f + erff(x * 0.7071067811865476f));
}

// ------------------------- weight transposes ---------------------------------
__global__ void prep_transpose(const float* __restrict__ Wp, const float* __restrict__ Wq,
                               const float* __restrict__ Wv, const float* __restrict__ Wih,
                               const float* __restrict__ Whh, const float* __restrict__ W1,
                               const float* __restrict__ W2) {
    int i = blockIdx.x * blockDim.x + threadIdx.x;
    int stride = gridDim.x * blockDim.x;
    for (int t = i; t < HH * DIN; t += stride) { int j = t / DIN, e = t % DIN; g_WpT[e * HH + j] = Wp[t]; }
    for (int t = i; t < HH * HH; t += stride) { int j = t / HH, e = t % HH; g_WqT[e * HH + j] = Wq[t]; }
    for (int t = i; t < HH * HH; t += stride) { int d = t / HH, e = t % HH; g_WvT[e * HH + d] = Wv[t]; }
    for (int t = i; t < 3 * HH * HH; t += stride) { int o = t / HH, d = t % HH; g_WihT[d * (3 * HH) + o] = Wih[t]; }
    for (int t = i; t < 3 * HH * HH; t += stride) { int o = t / HH, d = t % HH; g_WhhT[d * (3 * HH) + o] = Whh[t]; }
    for (int t = i; t < 2 * HH * HH; t += stride) { int p = t / HH, d = t % HH; g_W1T[d * (2 * HH) + p] = W1[t]; }
    for (int t = i; t < 2 * HH * HH; t += stride) { int j = t / (2 * HH), p = t % (2 * HH); g_W2T[p * HH + j] = W2[t]; }
}

// ------------------------- init slots + LN + q + qk + c (iteration 0) --------
__global__ __launch_bounds__(512) void init_lnq_kernel(const float* __restrict__ noise,
                                                       const float* __restrict__ smu,
                                                       const float* __restrict__ sls,
                                                       const float* __restrict__ gs,
                                                       const float* __restrict__ bs,
                                                       const float* __restrict__ bq,
                                                       const float* __restrict__ Wk,
                                                       const float* __restrict__ bk) {
    const int b = blockIdx.x;
    const int tid = threadIdx.x;
    const int wid = tid >> 5, lane = tid & 31;
    __shared__ float s_s[KK][HH];
    __shared__ float q_s[KK][HH];
    __shared__ float sl_s[KK * HH];
    __shared__ float part_s[4][KK][HH];
    __shared__ float red1[12], red2[12];

    if (tid < KK * HH) {
        float v = smu[tid] + expf(sls[tid]) * noise[b * KK * HH + tid];
        sl_s[tid] = v;
        g_slots[b * KK * HH + tid] = v;
        float a = wred(v), a2 = wred(v * v);
        if (lane == 0) { red1[wid] = a; red2[wid] = a2; }
    }
    __syncthreads();
    if (tid < KK * HH) {
        const int ka = tid >> 7, j = tid & 127;
        float mu = (red1[ka*4] + red1[ka*4+1] + red1[ka*4+2] + red1[ka*4+3]) * (1.0f / HH);
        float var = (red2[ka*4] + red2[ka*4+1] + red2[ka*4+2] + red2[ka*4+3]) * (1.0f / HH) - mu * mu;
        float rstd = rsqrtf(var + LNEPS);
        s_s[ka][j] = (sl_s[tid] - mu) * rstd * gs[j] + bs[j];
    }
    __syncthreads();
    {
        const int j = tid & 127, part = tid >> 7;
        const int e0 = part * 32;
        float a0 = 0.f, a1 = 0.f, a2 = 0.f;
        #pragma unroll 8
        for (int e = 0; e < 32; e++) {
            float wv = g_WqT[(e0 + e) * HH + j];
            a0 += s_s[0][e0 + e] * wv;
            a1 += s_s[1][e0 + e] * wv;
            a2 += s_s[2][e0 + e] * wv;
        }
        part_s[part][0][j] = a0; part_s[part][1][j] = a1; part_s[part][2][j] = a2;
    }
    __syncthreads();
    if (tid < KK * HH) {
        const int ka = tid >> 7, j = tid & 127;
        float s = bq[j];
        #pragma unroll
        for (int p = 0; p < 4; p++) s += part_s[p][ka][j];
        q_s[ka][j] = s;
    }
    __syncthreads();
    {
        const int j = tid & 127, part = tid >> 7;
        const int d0 = part * 32;
        float a0 = 0.f, a1 = 0.f, a2 = 0.f;
        #pragma unroll 8
        for (int d = 0; d < 32; d++) {
            float wv = Wk[(d0 + d) * HH + j];
            a0 += q_s[0][d0 + d] * wv;
            a1 += q_s[1][d0 + d] * wv;
            a2 += q_s[2][d0 + d] * wv;
        }
        part_s[part][0][j] = a0; part_s[part][1][j] = a1; part_s[part][2][j] = a2;
    }
    __syncthreads();
    if (tid < KK * HH) {
        const int ka = tid >> 7, j = tid & 127;
        float s = 0.f;
        #pragma unroll
        for (int p = 0; p < 4; p++) s += part_s[p][ka][j];
        g_qk[b * KK * HH + tid] = s * SCALE;
        float pr = wred(q_s[ka][j] * bk[j]);
        if (lane == 0) red1[wid] = pr;
    }
    __syncthreads();
    if (tid < KK)
        g_qc[b * KK + tid] = (red1[tid*4] + red1[tid*4+1] + red1[tid*4+2] + red1[tid*4+3]) * SCALE;
}

// ------------------------- fused projection + LayerNorm (f32x2) --------------
// Writes BOTH g_inputs [n][d] and g_inputsT [d][n] (via smem transpose stage).
#define TM 64
#define KB 16
__global__ __launch_bounds__(256) void proj_ln_kernel(const float* __restrict__ X,
                                                      const float* __restrict__ bp,
                                                      const float* __restrict__ gin,
                                                      const float* __restrict__ bin) {
    __shared__ union {
        struct { float xs_t[KB][66]; float ws[KB][HH]; } a;
        float stage[TM][129];
    } u;
    const int row0 = blockIdx.x * TM;
    const int tid = threadIdx.x;
    const int w = tid >> 5;
    const int l = tid & 31;

    u64 acc[4][4];
    #pragma unroll
    for (int p = 0; p < 4; p++)
        #pragma unroll
        for (int c = 0; c < 4; c++) acc[p][c] = 0ull;

    const int ld_row = tid >> 2;
    const int ld_seg = tid & 3;

    for (int k0 = 0; k0 < DIN; k0 += KB) {
        float4 xv = *(const float4*)(&X[(size_t)(row0 + ld_row) * DIN + k0 + ld_seg * 4]);
        u.a.xs_t[ld_seg * 4 + 0][ld_row] = xv.x;
        u.a.xs_t[ld_seg * 4 + 1][ld_row] = xv.y;
        u.a.xs_t[ld_seg * 4 + 2][ld_row] = xv.z;
        u.a.xs_t[ld_seg * 4 + 3][ld_row] = xv.w;
        #pragma unroll
        for (int i = 0; i < 2; i++) {
            int lin = i * 256 + tid;
            int kk = lin >> 5, jj = lin & 31;
            *(float4*)(&u.a.ws[kk][jj * 4]) = *(const float4*)(&g_WpT[(k0 + kk) * HH + jj * 4]);
        }
        __syncthreads();
        #pragma unroll
        for (int kk = 0; kk < KB; kk++) {
            float4 b4 = *(const float4*)(&u.a.ws[kk][l * 4]);
            u64 bx = pack2(b4.x, b4.x);
            u64 by = pack2(b4.y, b4.y);
            u64 bz = pack2(b4.z, b4.z);
            u64 bw = pack2(b4.w, b4.w);
            #pragma unroll
            for (int p = 0; p < 4; p++) {
                u64 a = *(const u64*)(&u.a.xs_t[kk][w * 8 + p * 2]);
                acc[p][0] = fma2(a, bx, acc[p][0]);
                acc[p][1] = fma2(a, by, acc[p][1]);
                acc[p][2] = fma2(a, bz, acc[p][2]);
                acc[p][3] = fma2(a, bw, acc[p][3]);
            }
        }
        __syncthreads();
    }

    const float4 bias = *(const float4*)(&bp[l * 4]);
    const float4 g4   = *(const float4*)(&gin[l * 4]);
    const float4 b4n  = *(const float4*)(&bin[l * 4]);

    #pragma unroll
    for (int p = 0; p < 4; p++) {
        float r0[4], r1[4];
        unpack2(acc[p][0], r0[0], r1[0]);
        unpack2(acc[p][1], r0[1], r1[1]);
        unpack2(acc[p][2], r0[2], r1[2]);
        unpack2(acc[p][3], r0[3], r1[3]);
        #pragma unroll
        for (int half = 0; half < 2; half++) {
            float* r = half ? r1 : r0;
            r[0] += bias.x; r[1] += bias.y; r[2] += bias.z; r[3] += bias.w;
            float s  = r[0] + r[1] + r[2] + r[3];
            float s2 = r[0]*r[0] + r[1]*r[1] + r[2]*r[2] + r[3]*r[3];
            s = wred(s); s2 = wred(s2);
            float mu = s * (1.0f / HH);
            float var = s2 * (1.0f / HH) - mu * mu;
            float rstd = rsqrtf(var + LNEPS);
            int rloc = w * 8 + p * 2 + half;
            int row = row0 + rloc;
            float4 o;
            o.x = (r[0] - mu) * rstd * g4.x + b4n.x;
            o.y = (r[1] - mu) * rstd * g4.y + b4n.y;
            o.z = (r[2] - mu) * rstd * g4.z + b4n.z;
            o.w = (r[3] - mu) * rstd * g4.w + b4n.w;
            *(float4*)(&g_inputs[(size_t)row * HH + l * 4]) = o;
            u.stage[rloc][l * 4 + 0] = o.x;
            u.stage[rloc][l * 4 + 1] = o.y;
            u.stage[rloc][l * 4 + 2] = o.z;
            u.stage[rloc][l * 4 + 3] = o.w;
        }
    }
    __syncthreads();

    // transposed write: g_inputsT[b][d][n]
    const int bb = row0 >> 10;
    const int nbase = row0 & 1023;
    #pragma unroll
    for (int it = 0; it < 8; it++) {
        int lin = it * 256 + tid;          // 0..2047 float4-units
        int d = lin >> 4;                  // 128 dims
        int seg = lin & 15;                // 16 float4 per dim (64 n)
        float4 v;
        v.x = u.stage[seg * 4 + 0][d];
        v.y = u.stage[seg * 4 + 1][d];
        v.z = u.stage[seg * 4 + 2][d];
        v.w = u.stage[seg * 4 + 3][d];
        *(float4*)(&g_inputsT[((size_t)bb * HH + d) * NN + nbase + seg * 4]) = v;
    }
}

// ------------------------- attention: two-pass, shuffle-free -----------------
// grid = BB*NSUB, 512 threads. sub covers 512 tokens.
__global__ __launch_bounds__(512) void attn_kernel(float* __restrict__ attn_out) {
    const int bx = blockIdx.x;
    const int b = bx >> 1, sub = bx & 1;
    const int n0 = sub * 512;
    const int tid = threadIdx.x;
    const int wid = tid >> 5, lane = tid & 31;
    __shared__ __align__(16) float qk_s[KK][HH];
    __shared__ float c_s[KK];
    __shared__ __align__(16) float a_s[KK][512];
    __shared__ float wacc[16][KK][HH];
    __shared__ float wsum_s[16][KK];

    if (tid < KK * HH) qk_s[0][tid] = g_qk[b * KK * HH + tid];
    if (tid < KK) c_s[tid] = g_qc[b * KK + tid];
    __syncthreads();

    // ---- Pass 1: logits per token (thread-local), softmax, attn write
    {
        const float* xT = g_inputsT + (size_t)b * HH * NN + n0 + tid;
        float d0 = c_s[0], d1 = c_s[1], d2 = c_s[2];
        #pragma unroll 4
        for (int dd = 0; dd < HH; dd += 4) {
            float4 q0 = *(const float4*)(&qk_s[0][dd]);
            float4 q1 = *(const float4*)(&qk_s[1][dd]);
            float4 q2 = *(const float4*)(&qk_s[2][dd]);
            float x0 = xT[(size_t)(dd + 0) * NN];
            float x1 = xT[(size_t)(dd + 1) * NN];
            float x2 = xT[(size_t)(dd + 2) * NN];
            float x3 = xT[(size_t)(dd + 3) * NN];
            d0 += x0 * q0.x + x1 * q0.y + x2 * q0.z + x3 * q0.w;
            d1 += x0 * q1.x + x1 * q1.y + x2 * q1.z + x3 * q1.w;
            d2 += x0 * q2.x + x1 * q2.y + x2 * q2.z + x3 * q2.w;
        }
        float m = fmaxf(d0, fmaxf(d1, d2));
        float e0 = expf(d0 - m), e1 = expf(d1 - m), e2 = expf(d2 - m);
        float inv = 1.0f / (e0 + e1 + e2);
        float a0 = e0 * inv, a1 = e1 * inv, a2 = e2 * inv;
        a_s[0][tid] = a0; a_s[1][tid] = a1; a_s[2][tid] = a2;
        attn_out[(size_t)b * KK * NN + 0 * NN + n0 + tid] = a0;
        attn_out[(size_t)b * KK * NN + 1 * NN + n0 + tid] = a1;
        attn_out[(size_t)b * KK * NN + 2 * NN + n0 + tid] = a2;
        float w0 = wred(a0), w1 = wred(a1), w2 = wred(a2);
        if (lane == 0) { wsum_s[wid][0] = w0; wsum_s[wid][1] = w1; wsum_s[wid][2] = w2; }
    }
    __syncthreads();

    // ---- Pass 2: f[ka][d] partials; dims per lane, tokens per warp-group
    {
        const int dbase = (tid & 31) * 4;
        const int grp = tid >> 5;             // 16 groups x 32 tokens
        float f0[4] = {0,0,0,0}, f1[4] = {0,0,0,0}, f2[4] = {0,0,0,0};
        const float* xp = g_inputs + ((size_t)b * NN + n0 + grp * 32) * HH + dbase;
        #pragma unroll 2
        for (int t4 = 0; t4 < 32; t4 += 4) {
            float4 a0 = *(const float4*)(&a_s[0][grp * 32 + t4]);
            float4 a1 = *(const float4*)(&a_s[1][grp * 32 + t4]);
            float4 a2 = *(const float4*)(&a_s[2][grp * 32 + t4]);
            float av0[4] = {a0.x, a0.y, a0.z, a0.w};
            float av1[4] = {a1.x, a1.y, a1.z, a1.w};
            float av2[4] = {a2.x, a2.y, a2.z, a2.w};
            #pragma unroll
            for (int q = 0; q < 4; q++) {
                float4 xv = *(const float4*)(&xp[(size_t)(t4 + q) * HH]);
                f0[0] += av0[q] * xv.x; f0[1] += av0[q] * xv.y; f0[2] += av0[q] * xv.z; f0[3] += av0[q] * xv.w;
                f1[0] += av1[q] * xv.x; f1[1] += av1[q] * xv.y; f1[2] += av1[q] * xv.z; f1[3] += av1[q] * xv.w;
                f2[0] += av2[q] * xv.x; f2[1] += av2[q] * xv.y; f2[2] += av2[q] * xv.z; f2[3] += av2[q] * xv.w;
            }
        }
        *(float4*)(&wacc[grp][0][dbase]) = make_float4(f0[0], f0[1], f0[2], f0[3]);
        *(float4*)(&wacc[grp][1][dbase]) = make_float4(f1[0], f1[1], f1[2], f1[3]);
        *(float4*)(&wacc[grp][2][dbase]) = make_float4(f2[0], f2[1], f2[2], f2[3]);
    }
    __syncthreads();

    if (tid < KK * HH) {
        const int ka = tid >> 7, e = tid & 127;
        float s = 0.f;
        #pragma unroll
        for (int g = 0; g < 16; g++) s += wacc[g][ka][e];
        g_updp[(b * NSUB + sub) * KK * HH + tid] = s;
    }
    if (tid < KK) {
        float s = 0.f;
        #pragma unroll
        for (int g = 0; g < 16; g++) s += wsum_s[g][tid];
        g_sumwp[(b * NSUB + sub) * KK + tid] = s;
    }
}

// ------------------------- post: 2 batches packed in f32x2 -------------------
// grid = BB/2, 1024 threads. All matvec math packed (lo=b0, hi=b1).
__global__ __launch_bounds__(1024) void post_kernel(const float* __restrict__ bv,
                                                    const float* __restrict__ bih,
                                                    const float* __restrict__ bhh,
                                                    const float* __restrict__ gm,
                                                    const float* __restrict__ bm,
                                                    const float* __restrict__ b1,
                                                    const float* __restrict__ b2,
                                                    const float* __restrict__ gs,
                                                    const float* __restrict__ bs,
                                                    const float* __restrict__ bq,
                                                    const float* __restrict__ Wk,
                                                    const float* __restrict__ bk,
                                                    float* __restrict__ out_slots) {
    const int b0 = blockIdx.x * 2, b1b = b0 + 1;
    const int tid = threadIdx.x;
    const int wid = tid >> 5, lane = tid & 31;

    __shared__ u64 upd2[384];   // also s_s in tail
    __shared__ u64 h2[384];
    __shared__ u64 x2[384];     // also q in tail
    __shared__ u64 hn2[384];
    __shared__ u64 m2[384];     // also new-slot stash
    __shared__ u64 t2[768];
    __shared__ union { u64 part[3072]; struct { u64 gi[1152]; u64 gh[1152]; } g; } pu;
    __shared__ u64 sw2[KK];
    __shared__ u64 red1[12], red2[12];

    // ---- Phase 0: gather + reduce NSUB partials, pack batches
    if (tid < 384) {
        float lo = g_updp[(b0 * NSUB + 0) * 384 + tid] + g_updp[(b0 * NSUB + 1) * 384 + tid];
        float hi = g_updp[(b1b * NSUB + 0) * 384 + tid] + g_updp[(b1b * NSUB + 1) * 384 + tid];
        upd2[tid] = pack2(lo, hi);
        h2[tid] = pack2(g_slots[b0 * 384 + tid], g_slots[b1b * 384 + tid]);
    }
    if (tid < KK) {
        float lo = g_sumwp[(b0 * NSUB + 0) * KK + tid] + g_sumwp[(b0 * NSUB + 1) * KK + tid];
        float hi = g_sumwp[(b1b * NSUB + 0) * KK + tid] + g_sumwp[(b1b * NSUB + 1) * KK + tid];
        sw2[tid] = pack2(lo, hi);
    }
    __syncthreads();

    // ---- Phase 1: x = upd @ Wv^T + sumw*bv (split-K8)
    {
        const int j = tid & 127, part = tid >> 7;
        const int e0 = part * 16;
        u64 a0 = 0ull, a1 = 0ull, a2 = 0ull;
        #pragma unroll
        for (int e = 0; e < 16; e++) {
            float wv = g_WvT[(e0 + e) * HH + j];
            u64 w2 = pack2(wv, wv);
            a0 = fma2(upd2[0 * 128 + e0 + e], w2, a0);
            a1 = fma2(upd2[1 * 128 + e0 + e], w2, a1);
            a2 = fma2(upd2[2 * 128 + e0 + e], w2, a2);
        }
        pu.part[part * 384 + 0 * 128 + j] = a0;
        pu.part[part * 384 + 1 * 128 + j] = a1;
        pu.part[part * 384 + 2 * 128 + j] = a2;
    }
    __syncthreads();
    if (tid < 384) {
        const int ka = tid >> 7, j = tid & 127;
        u64 s = mul2(sw2[ka], pack2(bv[j], bv[j]));
        #pragma unroll
        for (int p = 0; p < 8; p++) s = add2(s, pu.part[p * 384 + tid]);
        x2[tid] = s;
    }
    __syncthreads();

    // ---- Phase 2: GRU gates
    if (tid < 768) {
        const int is_hh = tid >= 384;
        const int o = is_hh ? tid - 384 : tid;
        const float* W = is_hh ? g_WhhT : g_WihT;
        const u64* src = is_hh ? h2 : x2;
        u64 a0 = 0ull, a1 = 0ull, a2 = 0ull;
        #pragma unroll 4
        for (int d = 0; d < HH; d++) {
            float wv = W[d * 384 + o];
            u64 w2 = pack2(wv, wv);
            a0 = fma2(src[0 * 128 + d], w2, a0);
            a1 = fma2(src[1 * 128 + d], w2, a1);
            a2 = fma2(src[2 * 128 + d], w2, a2);
        }
        float bb = is_hh ? bhh[o] : bih[o];
        u64 b2v = pack2(bb, bb);
        u64* dst = is_hh ? pu.g.gh : pu.g.gi;
        dst[0 * 384 + o] = add2(a0, b2v);
        dst[1 * 384 + o] = add2(a1, b2v);
        dst[2 * 384 + o] = add2(a2, b2v);
    }
    __syncthreads();

    // ---- Phase 3: gate combine + LN(gm, bm)
    if (tid < 384) {
        const int ka = tid >> 7, j = tid & 127;
        float irl, irh, izl, izh, inl, inh, hrl, hrh, hzl, hzh, hnl, hnh, hl, hh_;
        unpack2(pu.g.gi[ka * 384 + j],       irl, irh);
        unpack2(pu.g.gi[ka * 384 + 128 + j], izl, izh);
        unpack2(pu.g.gi[ka * 384 + 256 + j], inl, inh);
        unpack2(pu.g.gh[ka * 384 + j],       hrl, hrh);
        unpack2(pu.g.gh[ka * 384 + 128 + j], hzl, hzh);
        unpack2(pu.g.gh[ka * 384 + 256 + j], hnl, hnh);
        unpack2(h2[tid], hl, hh_);
        float rl = sigmoidf_(irl + hrl), rh = sigmoidf_(irh + hrh);
        float zl = sigmoidf_(izl + hzl), zh = sigmoidf_(izh + hzh);
        float nl = tanhf(inl + rl * hnl), nh = tanhf(inh + rh * hnh);
        float hwl = (1.0f - zl) * nl + zl * hl;
        float hwh = (1.0f - zh) * nh + zh * hh_;
        u64 hv = pack2(hwl, hwh);
        hn2[tid] = hv;
        u64 s1 = wred2(hv), s2 = wred2(mul2(hv, hv));
        if (lane == 0) { red1[wid] = s1; red2[wid] = s2; }
    }
    __syncthreads();
    if (tid < 384) {
        const int ka = tid >> 7, j = tid & 127;
        u64 s1 = add2(add2(red1[ka*4], red1[ka*4+1]), add2(red1[ka*4+2], red1[ka*4+3]));
        u64 s2 = add2(add2(red2[ka*4], red2[ka*4+1]), add2(red2[ka*4+2], red2[ka*4+3]));
        float s1l, s1h, s2l, s2h, hl, hh_;
        unpack2(s1, s1l, s1h); unpack2(s2, s2l, s2h);
        unpack2(hn2[tid], hl, hh_);
        float mul_ = s1l * (1.0f / HH), muh = s1h * (1.0f / HH);
        float rsl = rsqrtf(s2l * (1.0f / HH) - mul_ * mul_ + LNEPS);
        float rsh = rsqrtf(s2h * (1.0f / HH) - muh * muh + LNEPS);
        float gmj = gm[j], bmj = bm[j];
        m2[tid] = pack2((hl - mul_) * rsl * gmj + bmj, (hh_ - muh) * rsh * gmj + bmj);
    }
    __syncthreads();

    // ---- Phase 4: W1 + gelu (split-K4, 256 cols)
    {
        const int p = tid & 255, part = tid >> 8;
        const int d0 = part * 32;
        u64 a0 = 0ull, a1 = 0ull, a2 = 0ull;
        #pragma unroll 8
        for (int d = 0; d < 32; d++) {
            float wv = g_W1T[(d0 + d) * (2 * HH) + p];
            u64 w2 = pack2(wv, wv);
            a0 = fma2(m2[0 * 128 + d0 + d], w2, a0);
            a1 = fma2(m2[1 * 128 + d0 + d], w2, a1);
            a2 = fma2(m2[2 * 128 + d0 + d], w2, a2);
        }
        pu.part[part * 768 + 0 * 256 + p] = a0;
        pu.part[part * 768 + 1 * 256 + p] = a1;
        pu.part[part * 768 + 2 * 256 + p] = a2;
    }
    __syncthreads();
    if (tid < 768) {
        const int ka = tid >> 8, p = tid & 255;
        float bb = b1[p];
        u64 s = pack2(bb, bb);
        #pragma unroll
        for (int q = 0; q < 4; q++) s = add2(s, pu.part[q * 768 + ka * 256 + p]);
        float sl, sh;
        unpack2(s, sl, sh);
        t2[ka * 256 + p] = pack2(gelu_exact(sl), gelu_exact(sh));
    }
    __syncthreads();

    // ---- Phase 5: W2 + residual (split-K8)
    {
        const int j = tid & 127, part = tid >> 7;
        const int p0 = part * 32;
        u64 a0 = 0ull, a1 = 0ull, a2 = 0ull;
        #pragma unroll 8
        for (int p = 0; p < 32; p++) {
            float wv = g_W2T[(p0 + p) * HH + j];
            u64 w2 = pack2(wv, wv);
            a0 = fma2(t2[0 * 256 + p0 + p], w2, a0);
            a1 = fma2(t2[1 * 256 + p0 + p], w2, a1);
            a2 = fma2(t2[2 * 256 + p0 + p], w2, a2);
        }
        pu.part[part * 384 + 0 * 128 + j] = a0;
        pu.part[part * 384 + 1 * 128 + j] = a1;
        pu.part[part * 384 + 2 * 128 + j] = a2;
    }
    __syncthreads();
    if (tid < 384) {
        const int j = tid & 127;
        float bb = b2[j];
        u64 s = add2(hn2[tid], pack2(bb, bb));
        #pragma unroll
        for (int p = 0; p < 8; p++) s = add2(s, pu.part[p * 384 + tid]);
        float lo, hi;
        unpack2(s, lo, hi);
        g_slots[b0 * 384 + tid] = lo;  g_slots[b1b * 384 + tid] = hi;
        out_slots[b0 * 384 + tid] = lo; out_slots[b1b * 384 + tid] = hi;
        m2[tid] = s;                   // stash new slots
    }
    __syncthreads();

    // ================ TAIL: LN + q + qk + c for next iteration ================
    if (tid < 384) {
        u64 v = m2[tid];
        u64 s1 = wred2(v), s2 = wred2(mul2(v, v));
        if (lane == 0) { red1[wid] = s1; red2[wid] = s2; }
    }
    __syncthreads();
    if (tid < 384) {
        const int ka = tid >> 7, j = tid & 127;
        u64 s1 = add2(add2(red1[ka*4], red1[ka*4+1]), add2(red1[ka*4+2], red1[ka*4+3]));
        u64 s2 = add2(add2(red2[ka*4], red2[ka*4+1]), add2(red2[ka*4+2], red2[ka*4+3]));
        float s1l, s1h, s2l, s2h, vl, vh;
        unpack2(s1, s1l, s1h); unpack2(s2, s2l, s2h);
        unpack2(m2[tid], vl, vh);
        float mul_ = s1l * (1.0f / HH), muh = s1h * (1.0f / HH);
        float rsl = rsqrtf(s2l * (1.0f / HH) - mul_ * mul_ + LNEPS);
        float rsh = rsqrtf(s2h * (1.0f / HH) - muh * muh + LNEPS);
        float gsj = gs[j], bsj = bs[j];
        upd2[tid] = pack2((vl - mul_) * rsl * gsj + bsj, (vh - muh) * rsh * gsj + bsj);
    }
    __syncthreads();
    // q = s @ Wq^T + bq (split-K8)
    {
        const int j = tid & 127, part = tid >> 7;
        const int e0 = part * 16;
        u64 a0 = 0ull, a1 = 0ull, a2 = 0ull;
        #pragma unroll
        for (int e = 0; e < 16; e++) {
            float wv = g_WqT[(e0 + e) * HH + j];
            u64 w2 = pack2(wv, wv);
            a0 = fma2(upd2[0 * 128 + e0 + e], w2, a0);
            a1 = fma2(upd2[1 * 128 + e0 + e], w2, a1);
            a2 = fma2(upd2[2 * 128 + e0 + e], w2, a2);
        }
        pu.part[part * 384 + 0 * 128 + j] = a0;
        pu.part[part * 384 + 1 * 128 + j] = a1;
        pu.part[part * 384 + 2 * 128 + j] = a2;
    }
    __syncthreads();
    if (tid < 384) {
        const int j = tid & 127;
        float bb = bq[j];
        u64 s = pack2(bb, bb);
        #pragma unroll
        for (int p = 0; p < 8; p++) s = add2(s, pu.part[p * 384 + tid]);
        x2[tid] = s;
    }
    __syncthreads();
    // qk = SCALE * q @ Wk (split-K8)
    {
        const int j = tid & 127, part = tid >> 7;
        const int d0 = part * 16;
        u64 a0 = 0ull, a1 = 0ull, a2 = 0ull;
        #pragma unroll
        for (int d = 0; d < 16; d++) {
            float wv = Wk[(d0 + d) * HH + j];
            u64 w2 = pack2(wv, wv);
            a0 = fma2(x2[0 * 128 + d0 + d], w2, a0);
            a1 = fma2(x2[1 * 128 + d0 + d], w2, a1);
            a2 = fma2(x2[2 * 128 + d0 + d], w2, a2);
        }
        pu.part[part * 384 + 0 * 128 + j] = a0;
        pu.part[part * 384 + 1 * 128 + j] = a1;
        pu.part[part * 384 + 2 * 128 + j] = a2;
    }
    __syncthreads();
    if (tid < 384) {
        const int ka = tid >> 7, j = tid & 127;
        u64 s = 0ull;
        #pragma unroll
        for (int p = 0; p < 8; p++) s = add2(s, pu.part[p * 384 + tid]);
        float lo, hi;
        unpack2(s, lo, hi);
        g_qk[b0 * 384 + tid] = lo * SCALE;
        g_qk[b1b * 384 + tid] = hi * SCALE;
        float bkj = bk[j];
        u64 pr = wred2(mul2(x2[tid], pack2(bkj, bkj)));
        if (lane == 0) red1[wid] = pr;
    }
    __syncthreads();
    if (tid < KK) {
        u64 s = add2(add2(red1[tid*4], red1[tid*4+1]), add2(red1[tid*4+2], red1[tid*4+3]));
        float lo, hi;
        unpack2(s, lo, hi);
        g_qc[b0 * KK + tid] = lo * SCALE;
        g_qc[b1b * KK + tid] = hi * SCALE;
    }
}

// ------------------------- launch --------------------------------------------
extern "C" void kernel_launch(void* const* d_in, const int* in_sizes, int n_in,
                              void* d_out, int out_size) {
    const float* X       = (const float*)d_in[0];
    const float* noise   = (const float*)d_in[1];
    const float* slot_mu = (const float*)d_in[2];
    const float* slot_ls = (const float*)d_in[3];
    const float* Wp  = (const float*)d_in[4];
    const float* bp  = (const float*)d_in[5];
    const float* gin = (const float*)d_in[6];
    const float* bin = (const float*)d_in[7];
    const float* Wq  = (const float*)d_in[8];
    const float* bq  = (const float*)d_in[9];
    const float* Wk  = (const float*)d_in[10];
    const float* bk  = (const float*)d_in[11];
    const float* Wv  = (const float*)d_in[12];
    const float* bv  = (const float*)d_in[13];
    const float* Wih = (const float*)d_in[14];
    const float* bih = (const float*)d_in[15];
    const float* Whh = (const float*)d_in[16];
    const float* bhh = (const float*)d_in[17];
    const float* gs  = (const float*)d_in[18];
    const float* bs  = (const float*)d_in[19];
    const float* W1  = (const float*)d_in[20];
    const float* b1  = (const float*)d_in[21];
    const float* W2  = (const float*)d_in[22];
    const float* b2  = (const float*)d_in[23];
    const float* gm  = (const float*)d_in[24];
    const float* bm  = (const float*)d_in[25];

    float* out_slots = (float*)d_out;
    float* out_attn  = (float*)d_out + BB * KK * HH;

    prep_transpose<<<192, 256>>>(Wp, Wq, Wv, Wih, Whh, W1, W2);
    init_lnq_kernel<<<BB, 512>>>(noise, slot_mu, slot_ls, gs, bs, bq, Wk, bk);
    proj_ln_kernel<<<BN / TM, 256>>>(X, bp, gin, bin);

    for (int it = 0; it < 3; it++) {
        attn_kernel<<<BB * NSUB, 512>>>(out_attn);
        post_kernel<<<BB / 2, 1024>>>(bv, bih, bhh, gm, bm, b1, b2,
                                      gs, bs, bq, Wk, bk, out_slots);
    }
}

// round 9
// speedup vs baseline: 1.5098x; 1.1902x over previous
#include <cuda_runtime.h>
#include <math.h>

#define BB   128
#define NN   1024
#define DIN  192
#define HH   128
#define KK   3
#define BN   (BB*NN)
#define NSUB 2
#define SCALE 0.08838834764831845f   // 1/sqrt(128)
#define LNEPS 1e-5f

// ------------------------- device scratch ------------------------------------
__device__ float g_inputsT[(size_t)BN * HH];     // 64 MB, [b][d][n]
__device__ float g_WpT[DIN * HH];
__device__ float g_WqT[HH * HH];
__device__ float g_WvT[HH * HH];
__device__ float g_WihT[HH * 3 * HH];
__device__ float g_WhhT[HH * 3 * HH];
__device__ float g_W1T[HH * 2 * HH];
__device__ float g_W2T[2 * HH * HH];
__device__ float g_slots[BB * KK * HH];
__device__ float g_qk[BB * KK * HH];
__device__ float g_qc[BB * KK];
__device__ float g_updp[BB * NSUB * KK * HH];
__device__ float g_sumwp[BB * NSUB * KK];

typedef unsigned long long u64;

__device__ __forceinline__ u64 pack2(float lo, float hi) {
    u64 r; asm("mov.b64 %0, {%1,%2};" : "=l"(r) : "f"(lo), "f"(hi)); return r;
}
__device__ __forceinline__ void unpack2(u64 v, float& lo, float& hi) {
    asm("mov.b64 {%0,%1}, %2;" : "=f"(lo), "=f"(hi) : "l"(v));
}
__device__ __forceinline__ u64 fma2(u64 a, u64 b, u64 c) {
    u64 d; asm("fma.rn.f32x2 %0, %1, %2, %3;" : "=l"(d) : "l"(a), "l"(b), "l"(c)); return d;
}
__device__ __forceinline__ u64 add2(u64 a, u64 b) {
    u64 d; asm("add.rn.f32x2 %0, %1, %2;" : "=l"(d) : "l"(a), "l"(b)); return d;
}
__device__ __forceinline__ u64 mul2(u64 a, u64 b) {
    u64 d; asm("mul.rn.f32x2 %0, %1, %2;" : "=l"(d) : "l"(a), "l"(b)); return d;
}
__device__ __forceinline__ float wred(float v) {
    #pragma unroll
    for (int o = 16; o; o >>= 1) v += __shfl_xor_sync(0xFFFFFFFFu, v, o);
    return v;
}
__device__ __forceinline__ u64 wred2(u64 v) {
    #pragma unroll
    for (int o = 16; o; o >>= 1) v = add2(v, __shfl_xor_sync(0xFFFFFFFFu, v, o));
    return v;
}
__device__ __forceinline__ float sigmoidf_(float x) { return 1.0f / (1.0f + expf(-x)); }
__device__ __forceinline__ float gelu_exact(float x) {
    return 0.5f * x * (1.0f + erff(x * 0.7071067811865476f));
}

// ------------------------- weight transposes ---------------------------------
__global__ void prep_transpose(const float* __restrict__ Wp, const float* __restrict__ Wq,
                               const float* __restrict__ Wv, const float* __restrict__ Wih,
                               const float* __restrict__ Whh, const float* __restrict__ W1,
                               const float* __restrict__ W2) {
    int i = blockIdx.x * blockDim.x + threadIdx.x;
    int stride = gridDim.x * blockDim.x;
    for (int t = i; t < HH * DIN; t += stride) { int j = t / DIN, e = t % DIN; g_WpT[e * HH + j] = Wp[t]; }
    for (int t = i; t < HH * HH; t += stride) { int j = t / HH, e = t % HH; g_WqT[e * HH + j] = Wq[t]; }
    for (int t = i; t < HH * HH; t += stride) { int d = t / HH, e = t % HH; g_WvT[e * HH + d] = Wv[t]; }
    for (int t = i; t < 3 * HH * HH; t += stride) { int o = t / HH, d = t % HH; g_WihT[d * (3 * HH) + o] = Wih[t]; }
    for (int t = i; t < 3 * HH * HH; t += stride) { int o = t / HH, d = t % HH; g_WhhT[d * (3 * HH) + o] = Whh[t]; }
    for (int t = i; t < 2 * HH * HH; t += stride) { int p = t / HH, d = t % HH; g_W1T[d * (2 * HH) + p] = W1[t]; }
    for (int t = i; t < 2 * HH * HH; t += stride) { int j = t / (2 * HH), p = t % (2 * HH); g_W2T[p * HH + j] = W2[t]; }
}

// ------------------------- init slots + LN + q + qk + c (iteration 0) --------
__global__ __launch_bounds__(512) void init_lnq_kernel(const float* __restrict__ noise,
                                                       const float* __restrict__ smu,
                                                       const float* __restrict__ sls,
                                                       const float* __restrict__ gs,
                                                       const float* __restrict__ bs,
                                                       const float* __restrict__ bq,
                                                       const float* __restrict__ Wk,
                                                       const float* __restrict__ bk) {
    const int b = blockIdx.x;
    const int tid = threadIdx.x;
    const int wid = tid >> 5, lane = tid & 31;
    __shared__ float s_s[KK][HH];
    __shared__ float q_s[KK][HH];
    __shared__ float sl_s[KK * HH];
    __shared__ float part_s[4][KK][HH];
    __shared__ float red1[12], red2[12];

    if (tid < KK * HH) {
        float v = smu[tid] + expf(sls[tid]) * noise[b * KK * HH + tid];
        sl_s[tid] = v;
        g_slots[b * KK * HH + tid] = v;
        float a = wred(v), a2 = wred(v * v);
        if (lane == 0) { red1[wid] = a; red2[wid] = a2; }
    }
    __syncthreads();
    if (tid < KK * HH) {
        const int ka = tid >> 7, j = tid & 127;
        float mu = (red1[ka*4] + red1[ka*4+1] + red1[ka*4+2] + red1[ka*4+3]) * (1.0f / HH);
        float var = (red2[ka*4] + red2[ka*4+1] + red2[ka*4+2] + red2[ka*4+3]) * (1.0f / HH) - mu * mu;
        float rstd = rsqrtf(var + LNEPS);
        s_s[ka][j] = (sl_s[tid] - mu) * rstd * gs[j] + bs[j];
    }
    __syncthreads();
    {
        const int j = tid & 127, part = tid >> 7;
        const int e0 = part * 32;
        float a0 = 0.f, a1 = 0.f, a2 = 0.f;
        #pragma unroll 8
        for (int e = 0; e < 32; e++) {
            float wv = g_WqT[(e0 + e) * HH + j];
            a0 += s_s[0][e0 + e] * wv;
            a1 += s_s[1][e0 + e] * wv;
            a2 += s_s[2][e0 + e] * wv;
        }
        part_s[part][0][j] = a0; part_s[part][1][j] = a1; part_s[part][2][j] = a2;
    }
    __syncthreads();
    if (tid < KK * HH) {
        const int ka = tid >> 7, j = tid & 127;
        float s = bq[j];
        #pragma unroll
        for (int p = 0; p < 4; p++) s += part_s[p][ka][j];
        q_s[ka][j] = s;
    }
    __syncthreads();
    {
        const int j = tid & 127, part = tid >> 7;
        const int d0 = part * 32;
        float a0 = 0.f, a1 = 0.f, a2 = 0.f;
        #pragma unroll 8
        for (int d = 0; d < 32; d++) {
            float wv = Wk[(d0 + d) * HH + j];
            a0 += q_s[0][d0 + d] * wv;
            a1 += q_s[1][d0 + d] * wv;
            a2 += q_s[2][d0 + d] * wv;
        }
        part_s[part][0][j] = a0; part_s[part][1][j] = a1; part_s[part][2][j] = a2;
    }
    __syncthreads();
    if (tid < KK * HH) {
        const int ka = tid >> 7, j = tid & 127;
        float s = 0.f;
        #pragma unroll
        for (int p = 0; p < 4; p++) s += part_s[p][ka][j];
        g_qk[b * KK * HH + tid] = s * SCALE;
        float pr = wred(q_s[ka][j] * bk[j]);
        if (lane == 0) red1[wid] = pr;
    }
    __syncthreads();
    if (tid < KK)
        g_qc[b * KK + tid] = (red1[tid*4] + red1[tid*4+1] + red1[tid*4+2] + red1[tid*4+3]) * SCALE;
}

// ------------------------- fused projection + LayerNorm (f32x2) --------------
// Writes ONLY g_inputsT [b][d][n] (via smem transpose stage).
#define TM 64
#define KB 16
__global__ __launch_bounds__(256) void proj_ln_kernel(const float* __restrict__ X,
                                                      const float* __restrict__ bp,
                                                      const float* __restrict__ gin,
                                                      const float* __restrict__ bin) {
    __shared__ union {
        struct { float xs_t[KB][66]; float ws[KB][HH]; } a;
        float stage[TM][129];
    } u;
    const int row0 = blockIdx.x * TM;
    const int tid = threadIdx.x;
    const int w = tid >> 5;
    const int l = tid & 31;

    u64 acc[4][4];
    #pragma unroll
    for (int p = 0; p < 4; p++)
        #pragma unroll
        for (int c = 0; c < 4; c++) acc[p][c] = 0ull;

    const int ld_row = tid >> 2;
    const int ld_seg = tid & 3;

    for (int k0 = 0; k0 < DIN; k0 += KB) {
        float4 xv = *(const float4*)(&X[(size_t)(row0 + ld_row) * DIN + k0 + ld_seg * 4]);
        u.a.xs_t[ld_seg * 4 + 0][ld_row] = xv.x;
        u.a.xs_t[ld_seg * 4 + 1][ld_row] = xv.y;
        u.a.xs_t[ld_seg * 4 + 2][ld_row] = xv.z;
        u.a.xs_t[ld_seg * 4 + 3][ld_row] = xv.w;
        #pragma unroll
        for (int i = 0; i < 2; i++) {
            int lin = i * 256 + tid;
            int kk = lin >> 5, jj = lin & 31;
            *(float4*)(&u.a.ws[kk][jj * 4]) = *(const float4*)(&g_WpT[(k0 + kk) * HH + jj * 4]);
        }
        __syncthreads();
        #pragma unroll
        for (int kk = 0; kk < KB; kk++) {
            float4 b4 = *(const float4*)(&u.a.ws[kk][l * 4]);
            u64 bx = pack2(b4.x, b4.x);
            u64 by = pack2(b4.y, b4.y);
            u64 bz = pack2(b4.z, b4.z);
            u64 bw = pack2(b4.w, b4.w);
            #pragma unroll
            for (int p = 0; p < 4; p++) {
                u64 a = *(const u64*)(&u.a.xs_t[kk][w * 8 + p * 2]);
                acc[p][0] = fma2(a, bx, acc[p][0]);
                acc[p][1] = fma2(a, by, acc[p][1]);
                acc[p][2] = fma2(a, bz, acc[p][2]);
                acc[p][3] = fma2(a, bw, acc[p][3]);
            }
        }
        __syncthreads();
    }

    const float4 bias = *(const float4*)(&bp[l * 4]);
    const float4 g4   = *(const float4*)(&gin[l * 4]);
    const float4 b4n  = *(const float4*)(&bin[l * 4]);

    #pragma unroll
    for (int p = 0; p < 4; p++) {
        float r0[4], r1[4];
        unpack2(acc[p][0], r0[0], r1[0]);
        unpack2(acc[p][1], r0[1], r1[1]);
        unpack2(acc[p][2], r0[2], r1[2]);
        unpack2(acc[p][3], r0[3], r1[3]);
        #pragma unroll
        for (int half = 0; half < 2; half++) {
            float* r = half ? r1 : r0;
            r[0] += bias.x; r[1] += bias.y; r[2] += bias.z; r[3] += bias.w;
            float s  = r[0] + r[1] + r[2] + r[3];
            float s2 = r[0]*r[0] + r[1]*r[1] + r[2]*r[2] + r[3]*r[3];
            s = wred(s); s2 = wred(s2);
            float mu = s * (1.0f / HH);
            float var = s2 * (1.0f / HH) - mu * mu;
            float rstd = rsqrtf(var + LNEPS);
            int rloc = w * 8 + p * 2 + half;
            u.stage[rloc][l * 4 + 0] = (r[0] - mu) * rstd * g4.x + b4n.x;
            u.stage[rloc][l * 4 + 1] = (r[1] - mu) * rstd * g4.y + b4n.y;
            u.stage[rloc][l * 4 + 2] = (r[2] - mu) * rstd * g4.z + b4n.z;
            u.stage[rloc][l * 4 + 3] = (r[3] - mu) * rstd * g4.w + b4n.w;
        }
    }
    __syncthreads();

    // transposed write: g_inputsT[b][d][n]
    const int bb = row0 >> 10;
    const int nbase = row0 & 1023;
    #pragma unroll
    for (int it = 0; it < 8; it++) {
        int lin = it * 256 + tid;          // 0..2047 float4-units
        int d = lin >> 4;                  // 128 dims
        int seg = lin & 15;                // 16 float4 per dim (64 n)
        float4 v;
        v.x = u.stage[seg * 4 + 0][d];
        v.y = u.stage[seg * 4 + 1][d];
        v.z = u.stage[seg * 4 + 2][d];
        v.w = u.stage[seg * 4 + 3][d];
        *(float4*)(&g_inputsT[((size_t)bb * HH + d) * NN + nbase + seg * 4]) = v;
    }
}

// ------------------------- attention: two-pass, single array -----------------
// grid = BB*NSUB, 512 threads. Both passes read g_inputsT only.
__global__ __launch_bounds__(512) void attn_kernel(float* __restrict__ attn_out) {
    const int bx = blockIdx.x;
    const int b = bx >> 1, sub = bx & 1;
    const int n0 = sub * 512;
    const int tid = threadIdx.x;
    const int wid = tid >> 5, lane = tid & 31;
    __shared__ __align__(16) float qk_s[KK][HH];
    __shared__ float c_s[KK];
    __shared__ __align__(16) float a_s[KK][512];
    __shared__ float wsum_s[16][KK];

    if (tid < KK * HH) qk_s[0][tid] = g_qk[b * KK * HH + tid];
    if (tid < KK) c_s[tid] = g_qc[b * KK + tid];
    __syncthreads();

    const float* xT = g_inputsT + (size_t)b * HH * NN + n0;

    // ---- Pass 1: logits per token (thread-local), softmax, attn write
    {
        const float* xc = xT + tid;
        float d0 = c_s[0], d1 = c_s[1], d2 = c_s[2];
        #pragma unroll 4
        for (int dd = 0; dd < HH; dd += 4) {
            float4 q0 = *(const float4*)(&qk_s[0][dd]);
            float4 q1 = *(const float4*)(&qk_s[1][dd]);
            float4 q2 = *(const float4*)(&qk_s[2][dd]);
            float x0 = xc[(size_t)(dd + 0) * NN];
            float x1 = xc[(size_t)(dd + 1) * NN];
            float x2 = xc[(size_t)(dd + 2) * NN];
            float x3 = xc[(size_t)(dd + 3) * NN];
            d0 += x0 * q0.x + x1 * q0.y + x2 * q0.z + x3 * q0.w;
            d1 += x0 * q1.x + x1 * q1.y + x2 * q1.z + x3 * q1.w;
            d2 += x0 * q2.x + x1 * q2.y + x2 * q2.z + x3 * q2.w;
        }
        float m = fmaxf(d0, fmaxf(d1, d2));
        float e0 = expf(d0 - m), e1 = expf(d1 - m), e2 = expf(d2 - m);
        float inv = 1.0f / (e0 + e1 + e2);
        float a0 = e0 * inv, a1 = e1 * inv, a2 = e2 * inv;
        a_s[0][tid] = a0; a_s[1][tid] = a1; a_s[2][tid] = a2;
        attn_out[(size_t)b * KK * NN + 0 * NN + n0 + tid] = a0;
        attn_out[(size_t)b * KK * NN + 1 * NN + n0 + tid] = a1;
        attn_out[(size_t)b * KK * NN + 2 * NN + n0 + tid] = a2;
        float w0 = wred(a0), w1 = wred(a1), w2 = wred(a2);
        if (lane == 0) { wsum_s[wid][0] = w0; wsum_s[wid][1] = w1; wsum_s[wid][2] = w2; }
    }
    __syncthreads();

    // ---- Pass 2: f[ka][d] — warp owns 8 dims, lanes over 512 tokens
    {
        float* updp = g_updp + (size_t)(b * NSUB + sub) * KK * HH;
        #pragma unroll
        for (int dl = 0; dl < 8; dl++) {
            const int d = wid * 8 + dl;
            const float* xr = xT + (size_t)d * NN;
            float f0 = 0.f, f1 = 0.f, f2 = 0.f;
            #pragma unroll
            for (int it = 0; it < 4; it++) {
                const int n = it * 128 + lane * 4;
                float4 xv = *(const float4*)(&xr[n]);
                float4 a0 = *(const float4*)(&a_s[0][n]);
                float4 a1 = *(const float4*)(&a_s[1][n]);
                float4 a2 = *(const float4*)(&a_s[2][n]);
                f0 += xv.x * a0.x + xv.y * a0.y + xv.z * a0.z + xv.w * a0.w;
                f1 += xv.x * a1.x + xv.y * a1.y + xv.z * a1.z + xv.w * a1.w;
                f2 += xv.x * a2.x + xv.y * a2.y + xv.z * a2.z + xv.w * a2.w;
            }
            f0 = wred(f0); f1 = wred(f1); f2 = wred(f2);
            if (lane == 0) {
                updp[0 * HH + d] = f0;
                updp[1 * HH + d] = f1;
                updp[2 * HH + d] = f2;
            }
        }
    }
    if (tid < KK) {
        float s = 0.f;
        #pragma unroll
        for (int g = 0; g < 16; g++) s += wsum_s[g][tid];
        g_sumwp[(b * NSUB + sub) * KK + tid] = s;
    }
}

// ------------------------- post: 2 batches packed in f32x2 -------------------
// grid = BB/2, 1024 threads. All matvec math packed (lo=b0, hi=b1).
__global__ __launch_bounds__(1024) void post_kernel(const float* __restrict__ bv,
                                                    const float* __restrict__ bih,
                                                    const float* __restrict__ bhh,
                                                    const float* __restrict__ gm,
                                                    const float* __restrict__ bm,
                                                    const float* __restrict__ b1,
                                                    const float* __restrict__ b2,
                                                    const float* __restrict__ gs,
                                                    const float* __restrict__ bs,
                                                    const float* __restrict__ bq,
                                                    const float* __restrict__ Wk,
                                                    const float* __restrict__ bk,
                                                    float* __restrict__ out_slots) {
    const int b0 = blockIdx.x * 2, b1b = b0 + 1;
    const int tid = threadIdx.x;
    const int wid = tid >> 5, lane = tid & 31;

    __shared__ u64 upd2[384];   // also s_s in tail
    __shared__ u64 h2[384];
    __shared__ u64 x2[384];     // also q in tail
    __shared__ u64 hn2[384];
    __shared__ u64 m2[384];     // also new-slot stash
    __shared__ u64 t2[768];
    __shared__ union { u64 part[3072]; struct { u64 gi[1152]; u64 gh[1152]; } g; } pu;
    __shared__ u64 sw2[KK];
    __shared__ u64 red1[12], red2[12];

    // ---- Phase 0: gather + reduce NSUB partials, pack batches
    if (tid < 384) {
        float lo = g_updp[(b0 * NSUB + 0) * 384 + tid] + g_updp[(b0 * NSUB + 1) * 384 + tid];
        float hi = g_updp[(b1b * NSUB + 0) * 384 + tid] + g_updp[(b1b * NSUB + 1) * 384 + tid];
        upd2[tid] = pack2(lo, hi);
        h2[tid] = pack2(g_slots[b0 * 384 + tid], g_slots[b1b * 384 + tid]);
    }
    if (tid < KK) {
        float lo = g_sumwp[(b0 * NSUB + 0) * KK + tid] + g_sumwp[(b0 * NSUB + 1) * KK + tid];
        float hi = g_sumwp[(b1b * NSUB + 0) * KK + tid] + g_sumwp[(b1b * NSUB + 1) * KK + tid];
        sw2[tid] = pack2(lo, hi);
    }
    __syncthreads();

    // ---- Phase 1: x = upd @ Wv^T + sumw*bv (split-K8)
    {
        const int j = tid & 127, part = tid >> 7;
        const int e0 = part * 16;
        u64 a0 = 0ull, a1 = 0ull, a2 = 0ull;
        #pragma unroll
        for (int e = 0; e < 16; e++) {
            float wv = g_WvT[(e0 + e) * HH + j];
            u64 w2 = pack2(wv, wv);
            a0 = fma2(upd2[0 * 128 + e0 + e], w2, a0);
            a1 = fma2(upd2[1 * 128 + e0 + e], w2, a1);
            a2 = fma2(upd2[2 * 128 + e0 + e], w2, a2);
        }
        pu.part[part * 384 + 0 * 128 + j] = a0;
        pu.part[part * 384 + 1 * 128 + j] = a1;
        pu.part[part * 384 + 2 * 128 + j] = a2;
    }
    __syncthreads();
    if (tid < 384) {
        const int ka = tid >> 7, j = tid & 127;
        u64 s = mul2(sw2[ka], pack2(bv[j], bv[j]));
        #pragma unroll
        for (int p = 0; p < 8; p++) s = add2(s, pu.part[p * 384 + tid]);
        x2[tid] = s;
    }
    __syncthreads();

    // ---- Phase 2: GRU gates
    if (tid < 768) {
        const int is_hh = tid >= 384;
        const int o = is_hh ? tid - 384 : tid;
        const float* W = is_hh ? g_WhhT : g_WihT;
        const u64* src = is_hh ? h2 : x2;
        u64 a0 = 0ull, a1 = 0ull, a2 = 0ull;
        #pragma unroll 4
        for (int d = 0; d < HH; d++) {
            float wv = W[d * 384 + o];
            u64 w2 = pack2(wv, wv);
            a0 = fma2(src[0 * 128 + d], w2, a0);
            a1 = fma2(src[1 * 128 + d], w2, a1);
            a2 = fma2(src[2 * 128 + d], w2, a2);
        }
        float bb = is_hh ? bhh[o] : bih[o];
        u64 b2v = pack2(bb, bb);
        u64* dst = is_hh ? pu.g.gh : pu.g.gi;
        dst[0 * 384 + o] = add2(a0, b2v);
        dst[1 * 384 + o] = add2(a1, b2v);
        dst[2 * 384 + o] = add2(a2, b2v);
    }
    __syncthreads();

    // ---- Phase 3: gate combine + LN(gm, bm)
    if (tid < 384) {
        const int ka = tid >> 7, j = tid & 127;
        float irl, irh, izl, izh, inl, inh, hrl, hrh, hzl, hzh, hnl, hnh, hl, hh_;
        unpack2(pu.g.gi[ka * 384 + j],       irl, irh);
        unpack2(pu.g.gi[ka * 384 + 128 + j], izl, izh);
        unpack2(pu.g.gi[ka * 384 + 256 + j], inl, inh);
        unpack2(pu.g.gh[ka * 384 + j],       hrl, hrh);
        unpack2(pu.g.gh[ka * 384 + 128 + j], hzl, hzh);
        unpack2(pu.g.gh[ka * 384 + 256 + j], hnl, hnh);
        unpack2(h2[tid], hl, hh_);
        float rl = sigmoidf_(irl + hrl), rh = sigmoidf_(irh + hrh);
        float zl = sigmoidf_(izl + hzl), zh = sigmoidf_(izh + hzh);
        float nl = tanhf(inl + rl * hnl), nh = tanhf(inh + rh * hnh);
        float hwl = (1.0f - zl) * nl + zl * hl;
        float hwh = (1.0f - zh) * nh + zh * hh_;
        u64 hv = pack2(hwl, hwh);
        hn2[tid] = hv;
        u64 s1 = wred2(hv), s2 = wred2(mul2(hv, hv));
        if (lane == 0) { red1[wid] = s1; red2[wid] = s2; }
    }
    __syncthreads();
    if (tid < 384) {
        const int ka = tid >> 7, j = tid & 127;
        u64 s1 = add2(add2(red1[ka*4], red1[ka*4+1]), add2(red1[ka*4+2], red1[ka*4+3]));
        u64 s2 = add2(add2(red2[ka*4], red2[ka*4+1]), add2(red2[ka*4+2], red2[ka*4+3]));
        float s1l, s1h, s2l, s2h, hl, hh_;
        unpack2(s1, s1l, s1h); unpack2(s2, s2l, s2h);
        unpack2(hn2[tid], hl, hh_);
        float mul_ = s1l * (1.0f / HH), muh = s1h * (1.0f / HH);
        float rsl = rsqrtf(s2l * (1.0f / HH) - mul_ * mul_ + LNEPS);
        float rsh = rsqrtf(s2h * (1.0f / HH) - muh * muh + LNEPS);
        float gmj = gm[j], bmj = bm[j];
        m2[tid] = pack2((hl - mul_) * rsl * gmj + bmj, (hh_ - muh) * rsh * gmj + bmj);
    }
    __syncthreads();

    // ---- Phase 4: W1 + gelu (split-K4, 256 cols)
    {
        const int p = tid & 255, part = tid >> 8;
        const int d0 = part * 32;
        u64 a0 = 0ull, a1 = 0ull, a2 = 0ull;
        #pragma unroll 8
        for (int d = 0; d < 32; d++) {
            float wv = g_W1T[(d0 + d) * (2 * HH) + p];
            u64 w2 = pack2(wv, wv);
            a0 = fma2(m2[0 * 128 + d0 + d], w2, a0);
            a1 = fma2(m2[1 * 128 + d0 + d], w2, a1);
            a2 = fma2(m2[2 * 128 + d0 + d], w2, a2);
        }
        pu.part[part * 768 + 0 * 256 + p] = a0;
        pu.part[part * 768 + 1 * 256 + p] = a1;
        pu.part[part * 768 + 2 * 256 + p] = a2;
    }
    __syncthreads();
    if (tid < 768) {
        const int ka = tid >> 8, p = tid & 255;
        float bb = b1[p];
        u64 s = pack2(bb, bb);
        #pragma unroll
        for (int q = 0; q < 4; q++) s = add2(s, pu.part[q * 768 + ka * 256 + p]);
        float sl, sh;
        unpack2(s, sl, sh);
        t2[ka * 256 + p] = pack2(gelu_exact(sl), gelu_exact(sh));
    }
    __syncthreads();

    // ---- Phase 5: W2 + residual (split-K8)
    {
        const int j = tid & 127, part = tid >> 7;
        const int p0 = part * 32;
        u64 a0 = 0ull, a1 = 0ull, a2 = 0ull;
        #pragma unroll 8
        for (int p = 0; p < 32; p++) {
            float wv = g_W2T[(p0 + p) * HH + j];
            u64 w2 = pack2(wv, wv);
            a0 = fma2(t2[0 * 256 + p0 + p], w2, a0);
            a1 = fma2(t2[1 * 256 + p0 + p], w2, a1);
            a2 = fma2(t2[2 * 256 + p0 + p], w2, a2);
        }
        pu.part[part * 384 + 0 * 128 + j] = a0;
        pu.part[part * 384 + 1 * 128 + j] = a1;
        pu.part[part * 384 + 2 * 128 + j] = a2;
    }
    __syncthreads();
    if (tid < 384) {
        const int j = tid & 127;
        float bb = b2[j];
        u64 s = add2(hn2[tid], pack2(bb, bb));
        #pragma unroll
        for (int p = 0; p < 8; p++) s = add2(s, pu.part[p * 384 + tid]);
        float lo, hi;
        unpack2(s, lo, hi);
        g_slots[b0 * 384 + tid] = lo;  g_slots[b1b * 384 + tid] = hi;
        out_slots[b0 * 384 + tid] = lo; out_slots[b1b * 384 + tid] = hi;
        m2[tid] = s;                   // stash new slots
    }
    __syncthreads();

    // ================ TAIL: LN + q + qk + c for next iteration ================
    if (tid < 384) {
        u64 v = m2[tid];
        u64 s1 = wred2(v), s2 = wred2(mul2(v, v));
        if (lane == 0) { red1[wid] = s1; red2[wid] = s2; }
    }
    __syncthreads();
    if (tid < 384) {
        const int ka = tid >> 7, j = tid & 127;
        u64 s1 = add2(add2(red1[ka*4], red1[ka*4+1]), add2(red1[ka*4+2], red1[ka*4+3]));
        u64 s2 = add2(add2(red2[ka*4], red2[ka*4+1]), add2(red2[ka*4+2], red2[ka*4+3]));
        float s1l, s1h, s2l, s2h, vl, vh;
        unpack2(s1, s1l, s1h); unpack2(s2, s2l, s2h);
        unpack2(m2[tid], vl, vh);
        float mul_ = s1l * (1.0f / HH), muh = s1h * (1.0f / HH);
        float rsl = rsqrtf(s2l * (1.0f / HH) - mul_ * mul_ + LNEPS);
        float rsh = rsqrtf(s2h * (1.0f / HH) - muh * muh + LNEPS);
        float gsj = gs[j], bsj = bs[j];
        upd2[tid] = pack2((vl - mul_) * rsl * gsj + bsj, (vh - muh) * rsh * gsj + bsj);
    }
    __syncthreads();
    // q = s @ Wq^T + bq (split-K8)
    {
        const int j = tid & 127, part = tid >> 7;
        const int e0 = part * 16;
        u64 a0 = 0ull, a1 = 0ull, a2 = 0ull;
        #pragma unroll
        for (int e = 0; e < 16; e++) {
            float wv = g_WqT[(e0 + e) * HH + j];
            u64 w2 = pack2(wv, wv);
            a0 = fma2(upd2[0 * 128 + e0 + e], w2, a0);
            a1 = fma2(upd2[1 * 128 + e0 + e], w2, a1);
            a2 = fma2(upd2[2 * 128 + e0 + e], w2, a2);
        }
        pu.part[part * 384 + 0 * 128 + j] = a0;
        pu.part[part * 384 + 1 * 128 + j] = a1;
        pu.part[part * 384 + 2 * 128 + j] = a2;
    }
    __syncthreads();
    if (tid < 384) {
        const int j = tid & 127;
        float bb = bq[j];
        u64 s = pack2(bb, bb);
        #pragma unroll
        for (int p = 0; p < 8; p++) s = add2(s, pu.part[p * 384 + tid]);
        x2[tid] = s;
    }
    __syncthreads();
    // qk = SCALE * q @ Wk (split-K8)
    {
        const int j = tid & 127, part = tid >> 7;
        const int d0 = part * 16;
        u64 a0 = 0ull, a1 = 0ull, a2 = 0ull;
        #pragma unroll
        for (int d = 0; d < 16; d++) {
            float wv = Wk[(d0 + d) * HH + j];
            u64 w2 = pack2(wv, wv);
            a0 = fma2(x2[0 * 128 + d0 + d], w2, a0);
            a1 = fma2(x2[1 * 128 + d0 + d], w2, a1);
            a2 = fma2(x2[2 * 128 + d0 + d], w2, a2);
        }
        pu.part[part * 384 + 0 * 128 + j] = a0;
        pu.part[part * 384 + 1 * 128 + j] = a1;
        pu.part[part * 384 + 2 * 128 + j] = a2;
    }
    __syncthreads();
    if (tid < 384) {
        const int ka = tid >> 7, j = tid & 127;
        u64 s = 0ull;
        #pragma unroll
        for (int p = 0; p < 8; p++) s = add2(s, pu.part[p * 384 + tid]);
        float lo, hi;
        unpack2(s, lo, hi);
        g_qk[b0 * 384 + tid] = lo * SCALE;
        g_qk[b1b * 384 + tid] = hi * SCALE;
        float bkj = bk[j];
        u64 pr = wred2(mul2(x2[tid], pack2(bkj, bkj)));
        if (lane == 0) red1[wid] = pr;
    }
    __syncthreads();
    if (tid < KK) {
        u64 s = add2(add2(red1[tid*4], red1[tid*4+1]), add2(red1[tid*4+2], red1[tid*4+3]));
        float lo, hi;
        unpack2(s, lo, hi);
        g_qc[b0 * KK + tid] = lo * SCALE;
        g_qc[b1b * KK + tid] = hi * SCALE;
    }
}

// ------------------------- launch --------------------------------------------
extern "C" void kernel_launch(void* const* d_in, const int* in_sizes, int n_in,
                              void* d_out, int out_size) {
    const float* X       = (const float*)d_in[0];
    const float* noise   = (const float*)d_in[1];
    const float* slot_mu = (const float*)d_in[2];
    const float* slot_ls = (const float*)d_in[3];
    const float* Wp  = (const float*)d_in[4];
    const float* bp  = (const float*)d_in[5];
    const float* gin = (const float*)d_in[6];
    const float* bin = (const float*)d_in[7];
    const float* Wq  = (const float*)d_in[8];
    const float* bq  = (const float*)d_in[9];
    const float* Wk  = (const float*)d_in[10];
    const float* bk  = (const float*)d_in[11];
    const float* Wv  = (const float*)d_in[12];
    const float* bv  = (const float*)d_in[13];
    const float* Wih = (const float*)d_in[14];
    const float* bih = (const float*)d_in[15];
    const float* Whh = (const float*)d_in[16];
    const float* bhh = (const float*)d_in[17];
    const float* gs  = (const float*)d_in[18];
    const float* bs  = (const float*)d_in[19];
    const float* W1  = (const float*)d_in[20];
    const float* b1  = (const float*)d_in[21];
    const float* W2  = (const float*)d_in[22];
    const float* b2  = (const float*)d_in[23];
    const float* gm  = (const float*)d_in[24];
    const float* bm  = (const float*)d_in[25];

    float* out_slots = (float*)d_out;
    float* out_attn  = (float*)d_out + BB * KK * HH;

    prep_transpose<<<192, 256>>>(Wp, Wq, Wv, Wih, Whh, W1, W2);
    init_lnq_kernel<<<BB, 512>>>(noise, slot_mu, slot_ls, gs, bs, bq, Wk, bk);
    proj_ln_kernel<<<BN / TM, 256>>>(X, bp, gin, bin);

    for (int it = 0; it < 3; it++) {
        attn_kernel<<<BB * NSUB, 512>>>(out_attn);
        post_kernel<<<BB / 2, 1024>>>(bv, bih, bhh, gm, bm, b1, b2,
                                      gs, bs, bq, Wk, bk, out_slots);
    }
}